// round 10
// baseline (speedup 1.0000x reference)
#include <cuda_runtime.h>
#include <cuda_bf16.h>
#include <cstdint>
#include <cstddef>

#define BATCH 32
#define SEQ 2048
#define DA 32
#define HID 128
#define DS 64
#define NTOK (BATCH * SEQ)       /* 65536 */
#define TRANS_N (DS * DS)        /* 4096  */

/* Scratch: __device__ globals (no allocation allowed). */
__device__ __nv_bfloat16 g_h1h[(size_t)NTOK * HID];     /* 16 MB */
__device__ __nv_bfloat16 g_h1l[(size_t)NTOK * HID];     /* 16 MB */
__device__ __nv_bfloat16 g_w2hT[(size_t)TRANS_N * HID]; /* 1 MB, [n][k] */
__device__ __nv_bfloat16 g_w2lT[(size_t)TRANS_N * HID]; /* 1 MB */
__device__ float g_trans[(size_t)NTOK * TRANS_N];       /* 1 GiB */

/* ------------------------------------------------------------------ */
/* Kernel A: h1 = relu(relu(a@w0+b0)@w1 + b1); emit bf16 hi/lo split.  */
/* ------------------------------------------------------------------ */
__global__ __launch_bounds__(256) void mlp01_kernel(
    const float* __restrict__ actions, const float* __restrict__ w0,
    const float* __restrict__ b0, const float* __restrict__ w1,
    const float* __restrict__ b1)
{
    __shared__ float a_s[64 * DA];
    __shared__ float h0T[HID * 68];

    const int tid = threadIdx.x;
    const int tok0 = blockIdx.x * 64;

#pragma unroll
    for (int p = 0; p < 2; p++) {
        int u = p * 256 + tid;
        int tok = u >> 3;
        int c = (u & 7) * 4;
        float4 v = *reinterpret_cast<const float4*>(
            &actions[(size_t)(tok0 + tok) * DA + c]);
        a_s[tok * DA + c + 0] = v.x;
        a_s[tok * DA + c + 1] = v.y;
        a_s[tok * DA + c + 2] = v.z;
        a_s[tok * DA + c + 3] = v.w;
    }
    __syncthreads();

    const int j  = tid & 127;
    const int hi = tid >> 7;

    float w0c[DA];
#pragma unroll
    for (int k = 0; k < DA; k++) w0c[k] = w0[k * HID + j];
    const float b0v = b0[j];

    for (int o = 0; o < 32; o++) {
        int tok = o * 2 + hi;
        float acc = b0v;
#pragma unroll
        for (int k = 0; k < DA; k++) acc += a_s[tok * DA + k] * w0c[k];
        h0T[j * 68 + tok] = fmaxf(acc, 0.f);
    }
    __syncthreads();

    float accs[32];
#pragma unroll
    for (int m = 0; m < 32; m++) accs[m] = 0.f;
    const int m0 = hi * 32;

#pragma unroll 2
    for (int k = 0; k < HID; k++) {
        float wv = w1[k * HID + j];
        const float4* hp = reinterpret_cast<const float4*>(&h0T[k * 68 + m0]);
#pragma unroll
        for (int m4 = 0; m4 < 8; m4++) {
            float4 hv = hp[m4];
            accs[m4 * 4 + 0] += hv.x * wv;
            accs[m4 * 4 + 1] += hv.y * wv;
            accs[m4 * 4 + 2] += hv.z * wv;
            accs[m4 * 4 + 3] += hv.w * wv;
        }
    }
    const float b1v = b1[j];
#pragma unroll
    for (int m = 0; m < 32; m++) {
        float h = fmaxf(accs[m] + b1v, 0.f);
        __nv_bfloat16 h_hi = __float2bfloat16(h);
        __nv_bfloat16 h_lo = __float2bfloat16(h - __bfloat162float(h_hi));
        size_t idx = (size_t)(tok0 + m0 + m) * HID + j;
        g_h1h[idx] = h_hi;
        g_h1l[idx] = h_lo;
    }
}

/* ------------------------------------------------------------------ */
/* Kernel A2: transpose+split w2 [128,4096] -> w2hT/w2lT [4096,128].   */
/* ------------------------------------------------------------------ */
__global__ __launch_bounds__(256) void convw2_kernel(const float* __restrict__ w2)
{
    __shared__ float tile[32][33];
    const int n0 = blockIdx.x * 32;
    const int k0 = blockIdx.y * 32;
    const int tx = threadIdx.x;          /* 0..31 */
    const int ty = threadIdx.y;          /* 0..7  */

#pragma unroll
    for (int p = 0; p < 4; p++)
        tile[ty + p * 8][tx] = w2[(size_t)(k0 + ty + p * 8) * TRANS_N + n0 + tx];
    __syncthreads();

#pragma unroll
    for (int p = 0; p < 4; p++) {
        float v = tile[tx][ty + p * 8];
        __nv_bfloat16 vh = __float2bfloat16(v);
        __nv_bfloat16 vl = __float2bfloat16(v - __bfloat162float(vh));
        size_t o = (size_t)(n0 + ty + p * 8) * HID + k0 + tx;
        g_w2hT[o] = vh;
        g_w2lT[o] = vl;
    }
}

/* ------------------------------------------------------------------ */
/* Kernel B: split-bf16 GEMM via mma.sync (HMMA). Unchanged from R6.   */
/* ------------------------------------------------------------------ */
#define CHUNK_BYTES 16384u
#define STAGE_BYTES (2u * CHUNK_BYTES)
#define GB_DSMEM (2u * STAGE_BYTES)  /* 64 KB */

static __device__ __forceinline__ void ldmx4(uint32_t& r0, uint32_t& r1,
                                             uint32_t& r2, uint32_t& r3,
                                             uint32_t addr)
{
    asm volatile("ldmatrix.sync.aligned.m8n8.x4.shared.b16 {%0,%1,%2,%3}, [%4];"
                 : "=r"(r0), "=r"(r1), "=r"(r2), "=r"(r3) : "r"(addr));
}

static __device__ __forceinline__ void mma16816(float* c, const uint32_t* a,
                                                const uint32_t* b)
{
    asm volatile(
        "mma.sync.aligned.m16n8k16.row.col.f32.bf16.bf16.f32 "
        "{%0,%1,%2,%3}, {%4,%5,%6,%7}, {%8,%9}, {%0,%1,%2,%3};"
        : "+f"(c[0]), "+f"(c[1]), "+f"(c[2]), "+f"(c[3])
        : "r"(a[0]), "r"(a[1]), "r"(a[2]), "r"(a[3]), "r"(b[0]), "r"(b[1]));
}

__global__ __launch_bounds__(256, 2) void gemm_mma_kernel(
    const float* __restrict__ b2)
{
    extern __shared__ __align__(128) char sm[];

    const int tid = threadIdx.x;
    const int wid = tid >> 5;
    const int lane = tid & 31;
    const size_t m0 = (size_t)blockIdx.y * 128;
    const int n0 = blockIdx.x * 128;

    const int m_w = (wid & 1) * 64;
    const int n_w = (wid >> 1) * 32;

    const uint32_t smb = (uint32_t)__cvta_generic_to_shared(sm);

    auto load_chunk = [&](int c) {
        const __nv_bfloat16* ap = (c < 4) ? g_h1h : g_h1l;
        const __nv_bfloat16* bp = (c == 2 || c == 3) ? g_w2lT : g_w2hT;
        const int koff = (c & 1) * 64;
        const uint32_t Ab = smb + (uint32_t)(c & 1) * STAGE_BYTES;
        const uint32_t Bb = Ab + CHUNK_BYTES;
#pragma unroll
        for (int q = 0; q < 4; q++) {
            int u = q * 256 + tid;
            int row = u >> 3;
            int col8 = u & 7;
            uint32_t dst = (uint32_t)((row * 8 + (col8 ^ (row & 7))) * 16);
            const char* srcA = (const char*)(ap + (m0 + row) * HID + koff) + col8 * 16;
            const char* srcB = (const char*)(bp + (size_t)(n0 + row) * HID + koff) + col8 * 16;
            asm volatile("cp.async.cg.shared.global [%0], [%1], 16;"
                         :: "r"(Ab + dst), "l"(srcA));
            asm volatile("cp.async.cg.shared.global [%0], [%1], 16;"
                         :: "r"(Bb + dst), "l"(srcB));
        }
        asm volatile("cp.async.commit_group;" ::: "memory");
    };

    float acc[4][4][4];
#pragma unroll
    for (int i = 0; i < 4; i++)
#pragma unroll
        for (int j = 0; j < 4; j++)
#pragma unroll
            for (int q = 0; q < 4; q++) acc[i][j][q] = 0.f;

    const int a_row = lane & 15;
    const int a_ksel = lane >> 4;
    const int b_row = (lane & 7) | ((lane & 16) >> 1);
    const int b_ksel = (lane >> 3) & 1;

    load_chunk(0);

    for (int c = 0; c < 6; c++) {
        if (c < 5) load_chunk(c + 1);
        if (c < 5) asm volatile("cp.async.wait_group 1;" ::: "memory");
        else       asm volatile("cp.async.wait_group 0;" ::: "memory");
        __syncthreads();

        const uint32_t Ab = smb + (uint32_t)(c & 1) * STAGE_BYTES;
        const uint32_t Bb = Ab + CHUNK_BYTES;

#pragma unroll
        for (int k16 = 0; k16 < 4; k16++) {
            uint32_t afr[4][4];
            uint32_t bfr[4][2];
#pragma unroll
            for (int mi = 0; mi < 4; mi++) {
                int row = m_w + mi * 16 + a_row;
                int ku = (k16 * 2 + a_ksel) ^ (row & 7);
                ldmx4(afr[mi][0], afr[mi][1], afr[mi][2], afr[mi][3],
                      Ab + (uint32_t)((row * 8 + ku) * 16));
            }
#pragma unroll
            for (int np = 0; np < 2; np++) {
                int row = n_w + np * 16 + b_row;
                int ku = (k16 * 2 + b_ksel) ^ (row & 7);
                uint32_t r0, r1, r2, r3;
                ldmx4(r0, r1, r2, r3, Bb + (uint32_t)((row * 8 + ku) * 16));
                bfr[np * 2 + 0][0] = r0; bfr[np * 2 + 0][1] = r1;
                bfr[np * 2 + 1][0] = r2; bfr[np * 2 + 1][1] = r3;
            }
#pragma unroll
            for (int mi = 0; mi < 4; mi++)
#pragma unroll
                for (int ni = 0; ni < 4; ni++)
                    mma16816(acc[mi][ni], afr[mi], bfr[ni]);
        }
        __syncthreads();
    }

    float2 bias[4];
#pragma unroll
    for (int ni = 0; ni < 4; ni++) {
        int col = n0 + n_w + ni * 8 + (lane & 3) * 2;
        bias[ni] = *reinterpret_cast<const float2*>(&b2[col]);
    }
#pragma unroll
    for (int mi = 0; mi < 4; mi++) {
        size_t r0 = m0 + m_w + mi * 16 + (lane >> 2);
#pragma unroll
        for (int ni = 0; ni < 4; ni++) {
            int col = n0 + n_w + ni * 8 + (lane & 3) * 2;
            float2 v0 = make_float2(acc[mi][ni][0] + bias[ni].x,
                                    acc[mi][ni][1] + bias[ni].y);
            float2 v1 = make_float2(acc[mi][ni][2] + bias[ni].x,
                                    acc[mi][ni][3] + bias[ni].y);
            *reinterpret_cast<float2*>(&g_trans[r0 * TRANS_N + col]) = v0;
            *reinterpret_cast<float2*>(&g_trans[(r0 + 8) * TRANS_N + col]) = v1;
        }
    }
}

/* ------------------------------------------------------------------ */
/* Kernel C: warp-specialized RNN scan with deferred normalization.    */
/*  warps 0-3: matvec chain. Unnormalized state with exact power-of-2  */
/*   rescale, gain g=1/4 (exponent >> 2). Log-magnitude feedback loop  */
/*   x_t = x_{t-1} - x_{t-4}/4 has char. poly λ⁴-λ³+¼ with root moduli */
/*   {0.56, 0.889} — strictly stable (critical gain for delay-4 is     */
/*   2·sin(π/14)=0.445; R8's g=½ had modulus 1.022 → late-seq blowup). */
/*  warps 4-5: l2-norm + output store (one warp per step parity)       */
/*  warps 6-7: cp.async producers (8-stage ring)                       */
/* ------------------------------------------------------------------ */
#define SC_NSTAGE 8
#define SC_RING 16
#define SC_LAG 4
#define SC_DSMEM (SC_NSTAGE * TRANS_N * 4)   /* 128 KB */

static __device__ __forceinline__ unsigned ld_acq(const unsigned* p)
{
    unsigned v;
    asm volatile("ld.acquire.cta.shared.u32 %0, [%1];"
                 : "=r"(v) : "r"((uint32_t)__cvta_generic_to_shared(p)));
    return v;
}
static __device__ __forceinline__ void st_rel(unsigned* p, unsigned v)
{
    asm volatile("st.release.cta.shared.u32 [%0], %1;"
                 :: "r"((uint32_t)__cvta_generic_to_shared(p)), "r"(v));
}
static __device__ __forceinline__ void barx(int id, int cnt)
{
    asm volatile("bar.sync %0, %1;" :: "r"(id), "r"(cnt) : "memory");
}

__global__ __launch_bounds__(256, 1) void scan_kernel(
    const float* __restrict__ init_hidden, float* __restrict__ out)
{
    extern __shared__ __align__(16) float Tstage[];   /* [8][4096] */
    __shared__ __align__(16) float u_ring[SC_RING][DS];
    __shared__ float inv_ring[SC_RING];
    __shared__ float p_s[2 * DS];
    __shared__ float wsum[2];
    __shared__ unsigned uflag, sflag, nf[2];

    const int tid = threadIdx.x;
    const int b = blockIdx.x;
    const int lane = tid & 31;
    const float* trans = g_trans + (size_t)b * SEQ * TRANS_N;

    /* ---- init: flags + normalized initial hidden into u_ring[15] ---- */
    if (tid == 0) { uflag = 0; sflag = 0; nf[0] = 0; nf[1] = 0; }
    float v0 = 0.f;
    if (tid < 64) {
        v0 = init_hidden[tid];
        float s = v0 * v0;
        s += __shfl_xor_sync(0xffffffffu, s, 16);
        s += __shfl_xor_sync(0xffffffffu, s, 8);
        s += __shfl_xor_sync(0xffffffffu, s, 4);
        s += __shfl_xor_sync(0xffffffffu, s, 2);
        s += __shfl_xor_sync(0xffffffffu, s, 1);
        if (lane == 0) wsum[tid >> 5] = s;
    }
    __syncthreads();
    if (tid < 64) {
        float inv = 1.f / fmaxf(sqrtf(wsum[0] + wsum[1]), 1e-12f);
        u_ring[SC_RING - 1][tid] = v0 * inv;
    }
    __syncthreads();

    if (tid < 128) {
        /* ================= compute warps 0-3 ================= */
        const int j = tid & 63;
        const int iq = tid >> 6;
        for (int t = 0; t < SEQ; t++) {
            if (tid == 0) {
                while (ld_acq(&sflag) < (unsigned)(t + 1)) {}
                if (t >= SC_LAG) {
                    unsigned tp = t - SC_LAG;
                    while (ld_acq(&nf[tp & 1]) < (tp >> 1) + 1u) {}
                }
            }
            barx(1, 128);
            if (tid == 0) st_rel(&uflag, (unsigned)t);

            const float* Tcol = Tstage + (size_t)(t & 7) * TRANS_N + j;
            const float4* u4 = reinterpret_cast<const float4*>(
                &u_ring[(t + SC_RING - 1) & (SC_RING - 1)][iq * 32]);
            float a0 = 0.f, a1 = 0.f, a2 = 0.f, a3 = 0.f;
#pragma unroll
            for (int k8 = 0; k8 < 8; k8++) {
                float4 uv = u4[k8];
                const float* tp = Tcol + (iq * 32 + k8 * 4) * 64;
                a0 = fmaf(uv.x, tp[0], a0);
                a1 = fmaf(uv.y, tp[64], a1);
                a2 = fmaf(uv.z, tp[128], a2);
                a3 = fmaf(uv.w, tp[192], a3);
            }
            p_s[j * 2 + iq] = (a0 + a1) + (a2 + a3);
            barx(1, 128);

            if (tid < 64) {
                float z = p_s[j * 2] + p_s[j * 2 + 1];
                float u = fmaxf(z, 0.f);
                if (t >= SC_LAG) {
                    /* damped exact-p2 rescale: exponent(s) =               */
                    /* floor(exponent(inv_{t-4}) / 4). Strictly stable.     */
                    unsigned ib = __float_as_uint(
                        inv_ring[(t - SC_LAG) & (SC_RING - 1)]);
                    int e = (int)((ib >> 23) & 0xFFu) - 127;
                    e = max(-96, min(96, e));
                    float s = __uint_as_float(
                        (unsigned)(127 + (e >> 2)) << 23);
                    u *= s;
                }
                u_ring[t & (SC_RING - 1)][j] = u;
            }
        }
        barx(1, 128);
        if (tid == 0) st_rel(&uflag, (unsigned)SEQ);
    } else if (tid < 192) {
        /* ================= norm warps 4-5 (parity split) ================= */
        const int P = (tid >> 5) - 4;        /* 0: even steps, 1: odd steps */
        for (int t = P; t < SEQ; t += 2) {
            if (lane == 0)
                while (ld_acq(&uflag) < (unsigned)(t + 1)) {}
            __syncwarp();
            float2 u2 = *reinterpret_cast<const float2*>(
                &u_ring[t & (SC_RING - 1)][lane * 2]);
            float ss = fmaf(u2.x, u2.x, u2.y * u2.y);
            ss += __shfl_xor_sync(0xffffffffu, ss, 16);
            ss += __shfl_xor_sync(0xffffffffu, ss, 8);
            ss += __shfl_xor_sync(0xffffffffu, ss, 4);
            ss += __shfl_xor_sync(0xffffffffu, ss, 2);
            ss += __shfl_xor_sync(0xffffffffu, ss, 1);
            float inv = 1.f / fmaxf(sqrtf(ss), 1e-12f);
            *reinterpret_cast<float2*>(
                &out[((size_t)b * SEQ + t) * DS + lane * 2]) =
                make_float2(u2.x * inv, u2.y * inv);
            if (lane == 0) {
                inv_ring[t & (SC_RING - 1)] = inv;
                st_rel(&nf[P], (unsigned)((t >> 1) + 1));
            }
        }
    } else {
        /* ================= producer warps 6-7 ================= */
        const int p = tid - 192;
        const uint32_t Tb = (uint32_t)__cvta_generic_to_shared(Tstage);
        for (int s = 0; s < SEQ; s++) {
            if (p == 0 && s >= SC_NSTAGE)
                while (ld_acq(&uflag) < (unsigned)(s - (SC_NSTAGE - 1))) {}
            barx(2, 64);
            const float* src = trans + (size_t)s * TRANS_N;
            uint32_t dst = Tb + (uint32_t)(s & 7) * (TRANS_N * 4u);
#pragma unroll
            for (int q = 0; q < 16; q++) {
                int unit = q * 64 + p;
                asm volatile("cp.async.cg.shared.global [%0], [%1], 16;"
                             :: "r"(dst + (uint32_t)unit * 16u),
                                "l"(src + (size_t)unit * 4));
            }
            asm volatile("cp.async.commit_group;" ::: "memory");
            if (s >= 4) {
                asm volatile("cp.async.wait_group 4;" ::: "memory");
                barx(2, 64);
                if (p == 0) st_rel(&sflag, (unsigned)(s - 3));
            }
        }
        asm volatile("cp.async.wait_group 0;" ::: "memory");
        barx(2, 64);
        if (p == 0) st_rel(&sflag, (unsigned)SEQ);
    }
}

/* ------------------------------------------------------------------ */
extern "C" void kernel_launch(void* const* d_in, const int* in_sizes, int n_in,
                              void* d_out, int out_size)
{
    const float* actions = (const float*)d_in[0];
    const float* w0 = (const float*)d_in[1];
    const float* b0 = (const float*)d_in[2];
    const float* w1 = (const float*)d_in[3];
    const float* b1 = (const float*)d_in[4];
    const float* w2 = (const float*)d_in[5];
    const float* b2 = (const float*)d_in[6];
    const float* ih = (const float*)d_in[7];
    float* out = (float*)d_out;

    mlp01_kernel<<<NTOK / 64, 256>>>(actions, w0, b0, w1, b1);
    convw2_kernel<<<dim3(TRANS_N / 32, HID / 32), dim3(32, 8)>>>(w2);

    cudaFuncSetAttribute(gemm_mma_kernel,
                         cudaFuncAttributeMaxDynamicSharedMemorySize, GB_DSMEM);
    gemm_mma_kernel<<<dim3(TRANS_N / 128, NTOK / 128), 256, GB_DSMEM>>>(b2);

    cudaFuncSetAttribute(scan_kernel,
                         cudaFuncAttributeMaxDynamicSharedMemorySize, SC_DSMEM);
    scan_kernel<<<BATCH, 256, SC_DSMEM>>>(ih, out);
}

// round 11
// speedup vs baseline: 1.7081x; 1.7081x over previous
#include <cuda_runtime.h>
#include <cuda_bf16.h>
#include <cstdint>
#include <cstddef>

#define BATCH 32
#define SEQ 2048
#define DA 32
#define HID 128
#define DS 64
#define NTOK (BATCH * SEQ)       /* 65536 */
#define TRANS_N (DS * DS)        /* 4096  */

/* Scratch: __device__ globals (no allocation allowed). */
__device__ __nv_bfloat16 g_h1h[(size_t)NTOK * HID];     /* 16 MB */
__device__ __nv_bfloat16 g_h1l[(size_t)NTOK * HID];     /* 16 MB */
__device__ __nv_bfloat16 g_w2hT[(size_t)TRANS_N * HID]; /* 1 MB, [n][k] */
__device__ __nv_bfloat16 g_w2lT[(size_t)TRANS_N * HID]; /* 1 MB */
__device__ float g_trans[(size_t)NTOK * TRANS_N];       /* 1 GiB */

/* ------------------------------------------------------------------ */
/* Kernel A: h1 = relu(relu(a@w0+b0)@w1 + b1); emit bf16 hi/lo split.  */
/* ------------------------------------------------------------------ */
__global__ __launch_bounds__(256) void mlp01_kernel(
    const float* __restrict__ actions, const float* __restrict__ w0,
    const float* __restrict__ b0, const float* __restrict__ w1,
    const float* __restrict__ b1)
{
    __shared__ float a_s[64 * DA];
    __shared__ float h0T[HID * 68];

    const int tid = threadIdx.x;
    const int tok0 = blockIdx.x * 64;

#pragma unroll
    for (int p = 0; p < 2; p++) {
        int u = p * 256 + tid;
        int tok = u >> 3;
        int c = (u & 7) * 4;
        float4 v = *reinterpret_cast<const float4*>(
            &actions[(size_t)(tok0 + tok) * DA + c]);
        a_s[tok * DA + c + 0] = v.x;
        a_s[tok * DA + c + 1] = v.y;
        a_s[tok * DA + c + 2] = v.z;
        a_s[tok * DA + c + 3] = v.w;
    }
    __syncthreads();

    const int j  = tid & 127;
    const int hi = tid >> 7;

    float w0c[DA];
#pragma unroll
    for (int k = 0; k < DA; k++) w0c[k] = w0[k * HID + j];
    const float b0v = b0[j];

    for (int o = 0; o < 32; o++) {
        int tok = o * 2 + hi;
        float acc = b0v;
#pragma unroll
        for (int k = 0; k < DA; k++) acc += a_s[tok * DA + k] * w0c[k];
        h0T[j * 68 + tok] = fmaxf(acc, 0.f);
    }
    __syncthreads();

    float accs[32];
#pragma unroll
    for (int m = 0; m < 32; m++) accs[m] = 0.f;
    const int m0 = hi * 32;

#pragma unroll 2
    for (int k = 0; k < HID; k++) {
        float wv = w1[k * HID + j];
        const float4* hp = reinterpret_cast<const float4*>(&h0T[k * 68 + m0]);
#pragma unroll
        for (int m4 = 0; m4 < 8; m4++) {
            float4 hv = hp[m4];
            accs[m4 * 4 + 0] += hv.x * wv;
            accs[m4 * 4 + 1] += hv.y * wv;
            accs[m4 * 4 + 2] += hv.z * wv;
            accs[m4 * 4 + 3] += hv.w * wv;
        }
    }
    const float b1v = b1[j];
#pragma unroll
    for (int m = 0; m < 32; m++) {
        float h = fmaxf(accs[m] + b1v, 0.f);
        __nv_bfloat16 h_hi = __float2bfloat16(h);
        __nv_bfloat16 h_lo = __float2bfloat16(h - __bfloat162float(h_hi));
        size_t idx = (size_t)(tok0 + m0 + m) * HID + j;
        g_h1h[idx] = h_hi;
        g_h1l[idx] = h_lo;
    }
}

/* ------------------------------------------------------------------ */
/* Kernel A2: transpose+split w2 [128,4096] -> w2hT/w2lT [4096,128].   */
/* ------------------------------------------------------------------ */
__global__ __launch_bounds__(256) void convw2_kernel(const float* __restrict__ w2)
{
    __shared__ float tile[32][33];
    const int n0 = blockIdx.x * 32;
    const int k0 = blockIdx.y * 32;
    const int tx = threadIdx.x;          /* 0..31 */
    const int ty = threadIdx.y;          /* 0..7  */

#pragma unroll
    for (int p = 0; p < 4; p++)
        tile[ty + p * 8][tx] = w2[(size_t)(k0 + ty + p * 8) * TRANS_N + n0 + tx];
    __syncthreads();

#pragma unroll
    for (int p = 0; p < 4; p++) {
        float v = tile[tx][ty + p * 8];
        __nv_bfloat16 vh = __float2bfloat16(v);
        __nv_bfloat16 vl = __float2bfloat16(v - __bfloat162float(vh));
        size_t o = (size_t)(n0 + ty + p * 8) * HID + k0 + tx;
        g_w2hT[o] = vh;
        g_w2lT[o] = vl;
    }
}

/* ------------------------------------------------------------------ */
/* Kernel B: split-bf16 GEMM via mma.sync (HMMA). Unchanged from R6.   */
/* ------------------------------------------------------------------ */
#define CHUNK_BYTES 16384u
#define STAGE_BYTES (2u * CHUNK_BYTES)
#define GB_DSMEM (2u * STAGE_BYTES)  /* 64 KB */

static __device__ __forceinline__ void ldmx4(uint32_t& r0, uint32_t& r1,
                                             uint32_t& r2, uint32_t& r3,
                                             uint32_t addr)
{
    asm volatile("ldmatrix.sync.aligned.m8n8.x4.shared.b16 {%0,%1,%2,%3}, [%4];"
                 : "=r"(r0), "=r"(r1), "=r"(r2), "=r"(r3) : "r"(addr));
}

static __device__ __forceinline__ void mma16816(float* c, const uint32_t* a,
                                                const uint32_t* b)
{
    asm volatile(
        "mma.sync.aligned.m16n8k16.row.col.f32.bf16.bf16.f32 "
        "{%0,%1,%2,%3}, {%4,%5,%6,%7}, {%8,%9}, {%0,%1,%2,%3};"
        : "+f"(c[0]), "+f"(c[1]), "+f"(c[2]), "+f"(c[3])
        : "r"(a[0]), "r"(a[1]), "r"(a[2]), "r"(a[3]), "r"(b[0]), "r"(b[1]));
}

__global__ __launch_bounds__(256, 2) void gemm_mma_kernel(
    const float* __restrict__ b2)
{
    extern __shared__ __align__(128) char sm[];

    const int tid = threadIdx.x;
    const int wid = tid >> 5;
    const int lane = tid & 31;
    const size_t m0 = (size_t)blockIdx.y * 128;
    const int n0 = blockIdx.x * 128;

    const int m_w = (wid & 1) * 64;
    const int n_w = (wid >> 1) * 32;

    const uint32_t smb = (uint32_t)__cvta_generic_to_shared(sm);

    auto load_chunk = [&](int c) {
        const __nv_bfloat16* ap = (c < 4) ? g_h1h : g_h1l;
        const __nv_bfloat16* bp = (c == 2 || c == 3) ? g_w2lT : g_w2hT;
        const int koff = (c & 1) * 64;
        const uint32_t Ab = smb + (uint32_t)(c & 1) * STAGE_BYTES;
        const uint32_t Bb = Ab + CHUNK_BYTES;
#pragma unroll
        for (int q = 0; q < 4; q++) {
            int u = q * 256 + tid;
            int row = u >> 3;
            int col8 = u & 7;
            uint32_t dst = (uint32_t)((row * 8 + (col8 ^ (row & 7))) * 16);
            const char* srcA = (const char*)(ap + (m0 + row) * HID + koff) + col8 * 16;
            const char* srcB = (const char*)(bp + (size_t)(n0 + row) * HID + koff) + col8 * 16;
            asm volatile("cp.async.cg.shared.global [%0], [%1], 16;"
                         :: "r"(Ab + dst), "l"(srcA));
            asm volatile("cp.async.cg.shared.global [%0], [%1], 16;"
                         :: "r"(Bb + dst), "l"(srcB));
        }
        asm volatile("cp.async.commit_group;" ::: "memory");
    };

    float acc[4][4][4];
#pragma unroll
    for (int i = 0; i < 4; i++)
#pragma unroll
        for (int j = 0; j < 4; j++)
#pragma unroll
            for (int q = 0; q < 4; q++) acc[i][j][q] = 0.f;

    const int a_row = lane & 15;
    const int a_ksel = lane >> 4;
    const int b_row = (lane & 7) | ((lane & 16) >> 1);
    const int b_ksel = (lane >> 3) & 1;

    load_chunk(0);

    for (int c = 0; c < 6; c++) {
        if (c < 5) load_chunk(c + 1);
        if (c < 5) asm volatile("cp.async.wait_group 1;" ::: "memory");
        else       asm volatile("cp.async.wait_group 0;" ::: "memory");
        __syncthreads();

        const uint32_t Ab = smb + (uint32_t)(c & 1) * STAGE_BYTES;
        const uint32_t Bb = Ab + CHUNK_BYTES;

#pragma unroll
        for (int k16 = 0; k16 < 4; k16++) {
            uint32_t afr[4][4];
            uint32_t bfr[4][2];
#pragma unroll
            for (int mi = 0; mi < 4; mi++) {
                int row = m_w + mi * 16 + a_row;
                int ku = (k16 * 2 + a_ksel) ^ (row & 7);
                ldmx4(afr[mi][0], afr[mi][1], afr[mi][2], afr[mi][3],
                      Ab + (uint32_t)((row * 8 + ku) * 16));
            }
#pragma unroll
            for (int np = 0; np < 2; np++) {
                int row = n_w + np * 16 + b_row;
                int ku = (k16 * 2 + b_ksel) ^ (row & 7);
                uint32_t r0, r1, r2, r3;
                ldmx4(r0, r1, r2, r3, Bb + (uint32_t)((row * 8 + ku) * 16));
                bfr[np * 2 + 0][0] = r0; bfr[np * 2 + 0][1] = r1;
                bfr[np * 2 + 1][0] = r2; bfr[np * 2 + 1][1] = r3;
            }
#pragma unroll
            for (int mi = 0; mi < 4; mi++)
#pragma unroll
                for (int ni = 0; ni < 4; ni++)
                    mma16816(acc[mi][ni], afr[mi], bfr[ni]);
        }
        __syncthreads();
    }

    float2 bias[4];
#pragma unroll
    for (int ni = 0; ni < 4; ni++) {
        int col = n0 + n_w + ni * 8 + (lane & 3) * 2;
        bias[ni] = *reinterpret_cast<const float2*>(&b2[col]);
    }
#pragma unroll
    for (int mi = 0; mi < 4; mi++) {
        size_t r0 = m0 + m_w + mi * 16 + (lane >> 2);
#pragma unroll
        for (int ni = 0; ni < 4; ni++) {
            int col = n0 + n_w + ni * 8 + (lane & 3) * 2;
            float2 v0 = make_float2(acc[mi][ni][0] + bias[ni].x,
                                    acc[mi][ni][1] + bias[ni].y);
            float2 v1 = make_float2(acc[mi][ni][2] + bias[ni].x,
                                    acc[mi][ni][3] + bias[ni].y);
            *reinterpret_cast<float2*>(&g_trans[r0 * TRANS_N + col]) = v0;
            *reinterpret_cast<float2*>(&g_trans[(r0 + 8) * TRANS_N + col]) = v1;
        }
    }
}

/* ------------------------------------------------------------------ */
/* Kernel C: bulk-synchronous scan, role-split phases. Per step:       */
/*   phase A: warps 0-3 matvec(t); warp 4 norm+store(t-1) [off-path];  */
/*            warps 6-7 cp.async stage t+7 + wait_group 6              */
/*   phase B: threads 0-63 combine+relu+g=1/4 lag-4 p2 rescale (exact, */
/*            proven stable & bit-transparent in R10)                  */
/* Two __syncthreads per step; NO spin-wait flags (R10 lesson).        */
/* ------------------------------------------------------------------ */
#define SC_NSTAGE 8
#define SC_RING 16
#define SC_DSMEM (SC_NSTAGE * TRANS_N * 4)   /* 128 KB */

__global__ __launch_bounds__(256, 1) void scan_kernel(
    const float* __restrict__ init_hidden, float* __restrict__ out)
{
    extern __shared__ __align__(16) float Tstage[];   /* [8][4096] */
    __shared__ __align__(16) float u_ring[SC_RING][DS];
    __shared__ float inv_ring[SC_RING];
    __shared__ float p_s[2 * DS];
    __shared__ float wsum[2];

    const int tid = threadIdx.x;
    const int b = blockIdx.x;
    const int lane = tid & 31;
    const int wid = tid >> 5;
    const float* trans = g_trans + (size_t)b * SEQ * TRANS_N;
    const uint32_t Tb = (uint32_t)__cvta_generic_to_shared(Tstage);

    /* ---- init: normalized initial hidden into u_ring[15] ---- */
    float v0 = 0.f;
    if (tid < 64) {
        v0 = init_hidden[tid];
        float s = v0 * v0;
        s += __shfl_xor_sync(0xffffffffu, s, 16);
        s += __shfl_xor_sync(0xffffffffu, s, 8);
        s += __shfl_xor_sync(0xffffffffu, s, 4);
        s += __shfl_xor_sync(0xffffffffu, s, 2);
        s += __shfl_xor_sync(0xffffffffu, s, 1);
        if (lane == 0) wsum[tid >> 5] = s;
    }
    __syncthreads();
    if (tid < 64) {
        float inv = 1.f / fmaxf(sqrtf(wsum[0] + wsum[1]), 1e-12f);
        u_ring[SC_RING - 1][tid] = v0 * inv;
    }

    /* ---- prologue: producer warps load stages 0..6 ---- */
    if (wid >= 6) {
        const int p = tid - 192;   /* 0..63 */
        for (int s = 0; s < SC_NSTAGE - 1; s++) {
            const float* src = trans + (size_t)s * TRANS_N;
            uint32_t dst = Tb + (uint32_t)s * (TRANS_N * 4u);
#pragma unroll
            for (int q = 0; q < 16; q++) {
                int unit = q * 64 + p;
                asm volatile("cp.async.cg.shared.global [%0], [%1], 16;"
                             :: "r"(dst + (uint32_t)unit * 16u),
                                "l"(src + (size_t)unit * 4));
            }
            asm volatile("cp.async.commit_group;" ::: "memory");
        }
        asm volatile("cp.async.wait_group %0;" :: "n"(SC_NSTAGE - 2));
    }
    __syncthreads();

    for (int t = 0; t <= SEQ; t++) {
        /* ---------------- phase A ---------------- */
        if (wid < 4) {
            if (t < SEQ) {
                const int j = tid & 63;
                const int iq = tid >> 6;
                const float* Tcol = Tstage + (size_t)(t & 7) * TRANS_N + j;
                const float4* u4 = reinterpret_cast<const float4*>(
                    &u_ring[(t + SC_RING - 1) & (SC_RING - 1)][iq * 32]);
                float a0 = 0.f, a1 = 0.f, a2 = 0.f, a3 = 0.f;
#pragma unroll
                for (int k8 = 0; k8 < 8; k8++) {
                    float4 uv = u4[k8];
                    const float* tp = Tcol + (iq * 32 + k8 * 4) * 64;
                    a0 = fmaf(uv.x, tp[0], a0);
                    a1 = fmaf(uv.y, tp[64], a1);
                    a2 = fmaf(uv.z, tp[128], a2);
                    a3 = fmaf(uv.w, tp[192], a3);
                }
                p_s[j * 2 + iq] = (a0 + a1) + (a2 + a3);
            }
        } else if (wid == 4) {
            if (t >= 1) {
                const int tp = t - 1;
                float2 u2 = *reinterpret_cast<const float2*>(
                    &u_ring[tp & (SC_RING - 1)][lane * 2]);
                float ss = fmaf(u2.x, u2.x, u2.y * u2.y);
                ss += __shfl_xor_sync(0xffffffffu, ss, 16);
                ss += __shfl_xor_sync(0xffffffffu, ss, 8);
                ss += __shfl_xor_sync(0xffffffffu, ss, 4);
                ss += __shfl_xor_sync(0xffffffffu, ss, 2);
                ss += __shfl_xor_sync(0xffffffffu, ss, 1);
                float inv = 1.f / fmaxf(sqrtf(ss), 1e-12f);
                *reinterpret_cast<float2*>(
                    &out[((size_t)b * SEQ + tp) * DS + lane * 2]) =
                    make_float2(u2.x * inv, u2.y * inv);
                if (lane == 0) inv_ring[tp & (SC_RING - 1)] = inv;
            }
        } else if (wid >= 6) {
            const int p = tid - 192;
            int s = t + SC_NSTAGE - 1;
            if (s < SEQ) {
                const float* src = trans + (size_t)s * TRANS_N;
                uint32_t dst = Tb + (uint32_t)(s & 7) * (TRANS_N * 4u);
#pragma unroll
                for (int q = 0; q < 16; q++) {
                    int unit = q * 64 + p;
                    asm volatile("cp.async.cg.shared.global [%0], [%1], 16;"
                                 :: "r"(dst + (uint32_t)unit * 16u),
                                    "l"(src + (size_t)unit * 4));
                }
            }
            asm volatile("cp.async.commit_group;" ::: "memory");
            asm volatile("cp.async.wait_group %0;" :: "n"(SC_NSTAGE - 2));
        }
        __syncthreads();

        /* ---------------- phase B ---------------- */
        if (t < SEQ && tid < 64) {
            float z = p_s[tid * 2] + p_s[tid * 2 + 1];
            float u = fmaxf(z, 0.f);
            if (t >= 4) {
                /* g = 1/4 damped exact-p2 rescale (proven stable, R10) */
                unsigned ib = __float_as_uint(
                    inv_ring[(t - 4) & (SC_RING - 1)]);
                int e = (int)((ib >> 23) & 0xFFu) - 127;
                e = max(-96, min(96, e));
                float s = __uint_as_float((unsigned)(127 + (e >> 2)) << 23);
                u *= s;
            }
            u_ring[t & (SC_RING - 1)][tid] = u;
        }
        __syncthreads();
    }
}

/* ------------------------------------------------------------------ */
extern "C" void kernel_launch(void* const* d_in, const int* in_sizes, int n_in,
                              void* d_out, int out_size)
{
    const float* actions = (const float*)d_in[0];
    const float* w0 = (const float*)d_in[1];
    const float* b0 = (const float*)d_in[2];
    const float* w1 = (const float*)d_in[3];
    const float* b1 = (const float*)d_in[4];
    const float* w2 = (const float*)d_in[5];
    const float* b2 = (const float*)d_in[6];
    const float* ih = (const float*)d_in[7];
    float* out = (float*)d_out;

    mlp01_kernel<<<NTOK / 64, 256>>>(actions, w0, b0, w1, b1);
    convw2_kernel<<<dim3(TRANS_N / 32, HID / 32), dim3(32, 8)>>>(w2);

    cudaFuncSetAttribute(gemm_mma_kernel,
                         cudaFuncAttributeMaxDynamicSharedMemorySize, GB_DSMEM);
    gemm_mma_kernel<<<dim3(TRANS_N / 128, NTOK / 128), 256, GB_DSMEM>>>(b2);

    cudaFuncSetAttribute(scan_kernel,
                         cudaFuncAttributeMaxDynamicSharedMemorySize, SC_DSMEM);
    scan_kernel<<<BATCH, 256, SC_DSMEM>>>(ih, out);
}